// round 16
// baseline (speedup 1.0000x reference)
#include <cuda_runtime.h>
#include <cuda_bf16.h>
#include <cuda_fp16.h>
#include <math.h>
#include <stdint.h>

#define B_ 64
#define T_ 512
#define H_ 1024
#define E_ 512
#define V_ 32000
#define M_BT (B_ * T_)        // 32768

// ---------------- scratch (device globals; no allocation allowed) ----------------
__device__ float g_rnn_in[B_ * (E_ + H_)];
__device__ float g_bias_aT[H_ * B_];
__device__ float g_scores[M_BT];
__device__ float g_cat2[B_ * 2 * H_];
__device__ float g_gi[B_ * 3 * H_];
__device__ float g_gh[B_ * 3 * H_];
__device__ __half g_enc_h[(size_t)M_BT * H_];    // 64 MB fp16
__device__ __half g_w_h[H_ * H_];                // 2 MB fp16

// ======================= helpers =======================
__device__ __forceinline__ uint32_t smem_u32(const void* p) {
    uint32_t a;
    asm("{ .reg .u64 t; cvta.to.shared.u64 t, %1; cvt.u32.u64 %0, t; }" : "=r"(a) : "l"(p));
    return a;
}
#define CP_ASYNC16(dst, src) \
    asm volatile("cp.async.cg.shared.global [%0], [%1], 16;" :: "r"(dst), "l"(src))
#define CP_COMMIT() asm volatile("cp.async.commit_group;" ::: "memory")
#define CP_WAIT1() asm volatile("cp.async.wait_group 1;" ::: "memory")
#define CP_WAIT0() asm volatile("cp.async.wait_group 0;" ::: "memory")

__device__ __forceinline__ void ldmx4(uint32_t* r, uint32_t addr) {
    asm volatile("ldmatrix.sync.aligned.m8n8.x4.shared.b16 {%0,%1,%2,%3}, [%4];"
                 : "=r"(r[0]), "=r"(r[1]), "=r"(r[2]), "=r"(r[3]) : "r"(addr));
}
__device__ __forceinline__ void mma16816h(float* d, const uint32_t* a, uint32_t b0, uint32_t b1) {
    asm volatile("mma.sync.aligned.m16n8k16.row.col.f32.f16.f16.f32 "
                 "{%0,%1,%2,%3}, {%4,%5,%6,%7}, {%8,%9}, {%0,%1,%2,%3};"
                 : "+f"(d[0]), "+f"(d[1]), "+f"(d[2]), "+f"(d[3])
                 : "r"(a[0]), "r"(a[1]), "r"(a[2]), "r"(a[3]), "r"(b0), "r"(b1));
}
__device__ __forceinline__ uint2 cvt_h16(float4 x) {
    __align__(8) __half h[4];
    h[0] = __float2half_rn(x.x); h[1] = __float2half_rn(x.y);
    h[2] = __float2half_rn(x.z); h[3] = __float2half_rn(x.w);
    return *reinterpret_cast<uint2*>(h);
}

// ======================= tiling constants =======================
#define KSTEP 32
#define ROWB 80
// energy v7 (proven): fp16 1-pass, chunk=256 (32x64 warp tiles), KSTEP=64
#define EN_K 64
#define EN_ROWB 144
#define EN_A_T (128 * EN_ROWB)         // 18432
#define EN_B_T (256 * EN_ROWB)         // 36864
#define EN_STAGE (EN_A_T + EN_B_T)     // 55296
#define EN_RED_OFF (2 * EN_STAGE)      // 110592
#define SMEM_ENERGY (EN_RED_OFF + 512 * 4)   // 112640
// fc / generic fp16 gemm: BM=64, BN=128, KSTEP=32, 2 stages
#define FC_TA (64 * ROWB)              // 5120
#define FC_TB (128 * ROWB)             // 10240
#define FC_A 0
#define FC_B FC_TA
#define FC_STAGE (FC_TA + FC_TB)       // 15360
#define SMEM_FC (2 * FC_STAGE)         // 30720

#define ENC_BLOCKS ((M_BT * (H_ / 4)) / 256)   // 32768
#define W_BLOCKS ((H_ * (H_ / 4)) / 256)       // 1024

// ---------------- merged split: enc -> fp16, attn_W[:, H:] -> fp16 ----------------
__global__ void split_all_k(const float* __restrict__ enc,
                            const float* __restrict__ attnW,
                            __half* __restrict__ eh, __half* __restrict__ wh) {
    if (blockIdx.x < ENC_BLOCKS) {
        size_t i = (size_t)blockIdx.x * 256 + threadIdx.x;
        float4 x = reinterpret_cast<const float4*>(enc)[i];
        *reinterpret_cast<uint2*>(eh + 4 * i) = cvt_h16(x);
    } else {
        int i = (blockIdx.x - ENC_BLOCKS) * 256 + threadIdx.x;
        int r = i >> 8;
        int k4 = i & 255;
        float4 x = *(reinterpret_cast<const float4*>(attnW + (size_t)r * (2 * H_) + H_) + k4);
        *reinterpret_cast<uint2*>(wh + 4 * (size_t)i) = cvt_h16(x);
    }
}

// ---------------- embedding gather ----------------
__global__ void gather_emb_k(const int* __restrict__ x,
                             const float* __restrict__ embW,
                             float* __restrict__ rnn_in) {
    int b = blockIdx.x;
    int row = x[b];
    for (int e = threadIdx.x; e < E_; e += blockDim.x)
        rnn_in[b * (E_ + H_) + e] = embW[(size_t)row * E_ + e];
}

// ---------------- generic fp16 GEMM: C[64,N] = A[64,K] @ W[N,K]^T + bias ----------------
// tr=0: C[row*ldc + col]; tr=1: C[col*64 + row] (for bias_aT)
__global__ void __launch_bounds__(256, 2)
gemm_h_k(const float* __restrict__ A, int lda,
         const float* __restrict__ W, int ldw, int K,
         const float* __restrict__ bias,
         float* __restrict__ C, int ldc, int tr) {
    extern __shared__ char sm[];
    const uint32_t sb = smem_u32(sm);

    const int tid = threadIdx.x;
    const int wid = tid >> 5;
    const int lane = tid & 31;
    const int n0 = blockIdx.x * 128;
    const int mw = wid >> 2;
    const int nw = wid & 3;

    const int a_l = lane & 15;
    const int a_kh = (lane >> 4) << 3;
    const int b_nb = (lane & 7) + ((lane >> 4) << 3);
    const int b_kh = ((lane >> 3) & 1) << 3;
    const int g = lane >> 2;
    const int t2 = (lane & 3) << 1;

    float acc[2][4][4];
    #pragma unroll
    for (int mt = 0; mt < 2; mt++)
        #pragma unroll
        for (int nt = 0; nt < 4; nt++)
            #pragma unroll
            for (int k = 0; k < 4; k++) acc[mt][nt][k] = 0.f;

    const int aro[2] = {tid >> 3, (tid + 256) >> 3};
    const int bro[4] = {tid >> 3, (tid + 256) >> 3, (tid + 512) >> 3, (tid + 768) >> 3};
    const int qc = tid & 7;
    float4 Ar[2], Br[4];

    #define GH_LDG(it_) do {                                                        \
        int kb_ = (it_) * KSTEP;                                                    \
        _Pragma("unroll")                                                           \
        for (int j = 0; j < 2; j++)                                                 \
            Ar[j] = *(const float4*)&A[(size_t)aro[j] * lda + kb_ + qc * 4];        \
        _Pragma("unroll")                                                           \
        for (int j = 0; j < 4; j++)                                                 \
            Br[j] = *(const float4*)&W[(size_t)(n0 + bro[j]) * ldw + kb_ + qc * 4]; \
    } while (0)

    #define GH_STS(it_) do {                                                        \
        char* st_ = sm + ((it_) & 1) * FC_STAGE;                                    \
        _Pragma("unroll")                                                           \
        for (int j = 0; j < 2; j++)                                                 \
            *reinterpret_cast<uint2*>(st_ + FC_A + aro[j] * ROWB + qc * 8) = cvt_h16(Ar[j]); \
        _Pragma("unroll")                                                           \
        for (int j = 0; j < 4; j++)                                                 \
            *reinterpret_cast<uint2*>(st_ + FC_B + bro[j] * ROWB + qc * 8) = cvt_h16(Br[j]); \
    } while (0)

    const int total_it = K / KSTEP;
    GH_LDG(0);

    for (int it = 0; it < total_it; it++) {
        __syncthreads();
        GH_STS(it);
        if (it + 1 < total_it) GH_LDG(it + 1);
        __syncthreads();

        const uint32_t stg = sb + (it & 1) * FC_STAGE;
        #pragma unroll
        for (int ks = 0; ks < 2; ks++) {
            uint32_t Ah[2][4];
            #pragma unroll
            for (int mt = 0; mt < 2; mt++) {
                uint32_t off = (uint32_t)((mw * 32 + mt * 16 + a_l) * ROWB + (ks * 16 + a_kh) * 2);
                ldmx4(Ah[mt], stg + FC_A + off);
            }
            uint32_t Bh[2][4];
            #pragma unroll
            for (int np = 0; np < 2; np++) {
                uint32_t off = (uint32_t)((nw * 32 + np * 16 + b_nb) * ROWB + (ks * 16 + b_kh) * 2);
                ldmx4(Bh[np], stg + FC_B + off);
            }
            #pragma unroll
            for (int mt = 0; mt < 2; mt++)
                #pragma unroll
                for (int nt = 0; nt < 4; nt++) {
                    const int np = nt >> 1, pr = (nt & 1) * 2;
                    mma16816h(acc[mt][nt], Ah[mt], Bh[np][pr], Bh[np][pr + 1]);
                }
        }
    }

    #pragma unroll
    for (int nt = 0; nt < 4; nt++) {
        const int col0 = n0 + nw * 32 + nt * 8 + t2;
        const float c0 = __ldg(&bias[col0]);
        const float c1 = __ldg(&bias[col0 + 1]);
        #pragma unroll
        for (int mt = 0; mt < 2; mt++) {
            #pragma unroll
            for (int i = 0; i < 2; i++) {
                const int row = mw * 32 + mt * 16 + g + i * 8;
                float o0 = acc[mt][nt][i * 2 + 0] + c0;
                float o1 = acc[mt][nt][i * 2 + 1] + c1;
                if (tr) {
                    C[(size_t)col0 * 64 + row] = o0;
                    C[(size_t)(col0 + 1) * 64 + row] = o1;
                } else {
                    float2 o = {o0, o1};
                    *reinterpret_cast<float2*>(&C[(size_t)row * ldc + col0]) = o;
                }
            }
        }
    }
    #undef GH_LDG
    #undef GH_STS
}

// ---------------- energy GEMM v7 (proven): fp16 1-pass, chunk=256, 32x64 warp tiles ----------------
__global__ void __launch_bounds__(512, 1)
energy_mma_k(const __half* __restrict__ eh, const __half* __restrict__ wh,
             const float* __restrict__ biasT, const float* __restrict__ v,
             float* __restrict__ scores) {
    extern __shared__ char sm[];
    const uint32_t sb = smem_u32(sm);
    float* red = (float*)(sm + EN_RED_OFF);

    const int tid = threadIdx.x;
    const int wid = tid >> 5;
    const int lane = tid & 31;
    const int m0 = blockIdx.x * 128;
    const int mw = wid >> 2;
    const int nw = wid & 3;

    const int a_l = lane & 15;
    const int a_kh = (lane >> 4) << 3;
    const int b_nb = (lane & 7) + ((lane >> 4) << 3);
    const int b_kh = ((lane >> 3) & 1) << 3;
    const int g = lane >> 2;
    const int t2 = (lane & 3) << 1;

    float acc[2][8][4];
    float rowsum[4];
    #pragma unroll
    for (int i = 0; i < 4; i++) rowsum[i] = 0.f;

    const int total_it = 4 * 16;
    const int ar[2] = {tid >> 3, (tid + 512) >> 3};
    const int br[4] = {tid >> 3, (tid + 512) >> 3, (tid + 1024) >> 3, (tid + 1536) >> 3};
    const int cp_c = tid & 7;

    #define EN_CP(it_) do {                                                          \
        int chunk_ = (it_) >> 4;                                                     \
        int kb_ = ((it_) & 15) * EN_K;                                               \
        uint32_t stg_ = sb + ((it_) & 1) * EN_STAGE;                                 \
        _Pragma("unroll")                                                            \
        for (int j = 0; j < 2; j++)                                                  \
            CP_ASYNC16(stg_ + (uint32_t)(ar[j] * EN_ROWB + cp_c * 16),               \
                       eh + (size_t)(m0 + ar[j]) * H_ + kb_ + cp_c * 8);             \
        _Pragma("unroll")                                                            \
        for (int j = 0; j < 4; j++)                                                  \
            CP_ASYNC16(stg_ + EN_A_T + (uint32_t)(br[j] * EN_ROWB + cp_c * 16),      \
                       wh + (size_t)(chunk_ * 256 + br[j]) * H_ + kb_ + cp_c * 8);   \
        CP_COMMIT();                                                                 \
    } while (0)

    EN_CP(0);

    for (int it = 0; it < total_it; it++) {
        const int kt = it & 15;
        const int chunk = it >> 4;
        if (kt == 0) {
            #pragma unroll
            for (int mt = 0; mt < 2; mt++)
                #pragma unroll
                for (int nt = 0; nt < 8; nt++)
                    #pragma unroll
                    for (int k = 0; k < 4; k++) acc[mt][nt][k] = 0.f;
        }
        __syncthreads();
        if (it + 1 < total_it) { EN_CP(it + 1); CP_WAIT1(); }
        else { CP_WAIT0(); }
        __syncthreads();

        const uint32_t stg = sb + (it & 1) * EN_STAGE;
        #pragma unroll
        for (int ks = 0; ks < 4; ks++) {
            uint32_t Ah[2][4];
            #pragma unroll
            for (int mt = 0; mt < 2; mt++) {
                uint32_t off = (uint32_t)((mw * 32 + mt * 16 + a_l) * EN_ROWB + (ks * 16 + a_kh) * 2);
                ldmx4(Ah[mt], stg + off);
            }
            uint32_t Bh[4][4];
            #pragma unroll
            for (int np = 0; np < 4; np++) {
                uint32_t off = (uint32_t)((nw * 64 + np * 16 + b_nb) * EN_ROWB + (ks * 16 + b_kh) * 2);
                ldmx4(Bh[np], stg + EN_A_T + off);
            }
            #pragma unroll
            for (int mt = 0; mt < 2; mt++)
                #pragma unroll
                for (int np = 0; np < 4; np++) {
                    mma16816h(acc[mt][np * 2 + 0], Ah[mt], Bh[np][0], Bh[np][1]);
                    mma16816h(acc[mt][np * 2 + 1], Ah[mt], Bh[np][2], Bh[np][3]);
                }
        }

        if (kt == 15) {
            #pragma unroll
            for (int nt = 0; nt < 8; nt++) {
                const int col0 = chunk * 256 + nw * 64 + nt * 8 + t2;
                const float v0 = __ldg(&v[col0]);
                const float v1 = __ldg(&v[col0 + 1]);
                #pragma unroll
                for (int mt = 0; mt < 2; mt++) {
                    #pragma unroll
                    for (int i = 0; i < 2; i++) {
                        const int row = mw * 32 + mt * 16 + g + i * 8;
                        const int b = row & (B_ - 1);
                        float e0 = acc[mt][nt][i * 2 + 0] + __ldg(&biasT[(size_t)col0 * B_ + b]);
                        float e1 = acc[mt][nt][i * 2 + 1] + __ldg(&biasT[(size_t)(col0 + 1) * B_ + b]);
                        rowsum[mt * 2 + i] += fmaxf(e0, 0.f) * v0 + fmaxf(e1, 0.f) * v1;
                    }
                }
            }
        }
    }

    #pragma unroll
    for (int k = 0; k < 4; k++) {
        rowsum[k] += __shfl_xor_sync(0xFFFFFFFF, rowsum[k], 1);
        rowsum[k] += __shfl_xor_sync(0xFFFFFFFF, rowsum[k], 2);
    }
    __syncthreads();
    if ((lane & 3) == 0) {
        #pragma unroll
        for (int mt = 0; mt < 2; mt++)
            #pragma unroll
            for (int i = 0; i < 2; i++)
                red[nw * 128 + mw * 32 + mt * 16 + g + i * 8] = rowsum[mt * 2 + i];
    }
    __syncthreads();
    if (tid < 128) {
        float s = red[tid] + red[128 + tid] + red[256 + tid] + red[384 + tid];
        scores[m0 + tid] = s;
    }
    #undef EN_CP
}

// ---------------- softmax over T ----------------
__global__ void softmax_k(const float* __restrict__ scores,
                          float* __restrict__ attn_w_out) {
    int b = blockIdx.x;
    int t = threadIdx.x;
    __shared__ float sh[512];
    float s = scores[t * B_ + b];
    sh[t] = s;
    __syncthreads();
    for (int off = 256; off > 0; off >>= 1) {
        if (t < off) sh[t] = fmaxf(sh[t], sh[t + off]);
        __syncthreads();
    }
    float mx = sh[0];
    __syncthreads();
    float e = expf(s - mx);
    sh[t] = e;
    __syncthreads();
    for (int off = 256; off > 0; off >>= 1) {
        if (t < off) sh[t] += sh[t + off];
        __syncthreads();
    }
    attn_w_out[b * T_ + t] = e / sh[0];
}

// ---------------- context = attn_w @ enc (float4, unroll 8) ----------------
__global__ void context_k(const float4* __restrict__ enc4,
                          const float* __restrict__ attn_w,
                          float* __restrict__ rnn_in,
                          float* __restrict__ cat2) {
    int b = blockIdx.y;
    int h4 = blockIdx.x * 128 + threadIdx.x;
    __shared__ float w[T_];
    for (int t = threadIdx.x; t < T_; t += 128) w[t] = attn_w[b * T_ + t];
    __syncthreads();
    float4 acc = {0.f, 0.f, 0.f, 0.f};
    #pragma unroll 8
    for (int t = 0; t < T_; t++) {
        float4 e = enc4[(size_t)(t * B_ + b) * (H_ / 4) + h4];
        float wt = w[t];
        acc.x = fmaf(wt, e.x, acc.x);
        acc.y = fmaf(wt, e.y, acc.y);
        acc.z = fmaf(wt, e.z, acc.z);
        acc.w = fmaf(wt, e.w, acc.w);
    }
    int h = h4 * 4;
    *reinterpret_cast<float4*>(&rnn_in[b * (E_ + H_) + E_ + h]) = acc;
    *reinterpret_cast<float4*>(&cat2[b * (2 * H_) + H_ + h]) = acc;
}

// ---------------- GRU gates (full gi/gh, biases already folded in) ----------------
__global__ void gates_k(const float* __restrict__ gi,
                        const float* __restrict__ gh,
                        const float* __restrict__ lh,
                        float* __restrict__ hnew_out,
                        float* __restrict__ cat2) {
    int b = blockIdx.x;
    for (int h = threadIdx.x; h < H_; h += blockDim.x) {
        float gi0 = gi[(size_t)b * 3 * H_ + h];
        float gi1 = gi[(size_t)b * 3 * H_ + H_ + h];
        float gi2 = gi[(size_t)b * 3 * H_ + 2 * H_ + h];
        float gh0 = gh[(size_t)b * 3 * H_ + h];
        float gh1 = gh[(size_t)b * 3 * H_ + H_ + h];
        float gh2 = gh[(size_t)b * 3 * H_ + 2 * H_ + h];
        float r = 1.f / (1.f + expf(-(gi0 + gh0)));
        float z = 1.f / (1.f + expf(-(gi1 + gh1)));
        float n = tanhf(gi2 + r * gh2);
        float hp = lh[b * H_ + h];
        float hn = (1.f - z) * n + z * hp;
        hnew_out[b * H_ + h] = hn;
        cat2[b * (2 * H_) + h] = hn;
    }
}

// ---------------- log_softmax in-place ----------------
__global__ void logsoftmax_k(float* __restrict__ logits) {
    int b = blockIdx.x;
    int tid = threadIdx.x;
    __shared__ float sh[1024];
    float* row = logits + (size_t)b * V_;
    float mx = -1e30f;
    for (int n = tid; n < V_; n += 1024) mx = fmaxf(mx, row[n]);
    sh[tid] = mx;
    __syncthreads();
    for (int off = 512; off > 0; off >>= 1) {
        if (tid < off) sh[tid] = fmaxf(sh[tid], sh[tid + off]);
        __syncthreads();
    }
    mx = sh[0];
    __syncthreads();
    float sum = 0.f;
    for (int n = tid; n < V_; n += 1024) sum += expf(row[n] - mx);
    sh[tid] = sum;
    __syncthreads();
    for (int off = 512; off > 0; off >>= 1) {
        if (tid < off) sh[tid] += sh[tid + off];
        __syncthreads();
    }
    float lse = mx + logf(sh[0]);
    for (int n = tid; n < V_; n += 1024) row[n] -= lse;
}

// ---------------- launch ----------------
extern "C" void kernel_launch(void* const* d_in, const int* in_sizes, int n_in,
                              void* d_out, int out_size) {
    const int*   x    = (const int*)d_in[0];
    const float* lh   = (const float*)d_in[1];
    const float* enc  = (const float*)d_in[2];
    const float* embW = (const float*)d_in[3];
    const float* attW = (const float*)d_in[4];
    const float* attb = (const float*)d_in[5];
    const float* v    = (const float*)d_in[6];
    const float* Wih  = (const float*)d_in[7];
    const float* Whh  = (const float*)d_in[8];
    const float* bih  = (const float*)d_in[9];
    const float* bhh  = (const float*)d_in[10];
    const float* fcW  = (const float*)d_in[11];
    const float* fcb  = (const float*)d_in[12];

    float* out      = (float*)d_out;
    float* out_logp = out;
    float* out_h    = out + (size_t)B_ * V_;
    float* out_w    = out_h + (size_t)B_ * H_;

    float *rnn_in, *bias_aT, *scoresp, *cat2, *gi, *gh;
    __half *eh, *wh;
    cudaGetSymbolAddress((void**)&rnn_in,  g_rnn_in);
    cudaGetSymbolAddress((void**)&bias_aT, g_bias_aT);
    cudaGetSymbolAddress((void**)&scoresp, g_scores);
    cudaGetSymbolAddress((void**)&cat2,    g_cat2);
    cudaGetSymbolAddress((void**)&gi,      g_gi);
    cudaGetSymbolAddress((void**)&gh,      g_gh);
    cudaGetSymbolAddress((void**)&eh,      g_enc_h);
    cudaGetSymbolAddress((void**)&wh,      g_w_h);

    cudaFuncSetAttribute(energy_mma_k, cudaFuncAttributeMaxDynamicSharedMemorySize, SMEM_ENERGY);
    cudaFuncSetAttribute(gemm_h_k, cudaFuncAttributeMaxDynamicSharedMemorySize, SMEM_FC);

    // launch order: energy_mma_k stays launch #4 (ncu captures the 4th launch)
    split_all_k<<<ENC_BLOCKS + W_BLOCKS, 256>>>(enc, attW, eh, wh);                            // 1
    // bias_aT[h][b] = attb[h] + lh @ attW[:, :H]^T  (transposed store)
    gemm_h_k<<<H_ / 128, 256, SMEM_FC>>>(lh, H_, attW, 2 * H_, H_, attb, bias_aT, 0, 1);       // 2
    gather_emb_k<<<B_, 128>>>(x, embW, rnn_in);                                                // 3
    energy_mma_k<<<M_BT / 128, 512, SMEM_ENERGY>>>(eh, wh, bias_aT, v, scoresp);               // 4
    softmax_k<<<B_, 512>>>(scoresp, out_w);                                                    // 5
    context_k<<<dim3(2, B_), 128>>>((const float4*)enc, out_w, rnn_in, cat2);                  // 6
    // gi = rnn_in @ Wih^T + bih  [64, 3072]
    gemm_h_k<<<3 * H_ / 128, 256, SMEM_FC>>>(rnn_in, E_ + H_, Wih, E_ + H_, E_ + H_, bih, gi, 3 * H_, 0);  // 7
    // gh = lh @ Whh^T + bhh  [64, 3072]
    gemm_h_k<<<3 * H_ / 128, 256, SMEM_FC>>>(lh, H_, Whh, H_, H_, bhh, gh, 3 * H_, 0);         // 8
    gates_k<<<B_, 256>>>(gi, gh, lh, out_h, cat2);                                             // 9
    // fc logits
    gemm_h_k<<<V_ / 128, 256, SMEM_FC>>>(cat2, 2 * H_, fcW, 2 * H_, 2 * H_, fcb, out_logp, V_, 0);  // 10
    logsoftmax_k<<<B_, 1024>>>(out_logp);                                                      // 11
}

// round 17
// speedup vs baseline: 1.0821x; 1.0821x over previous
#include <cuda_runtime.h>
#include <cuda_bf16.h>
#include <cuda_fp16.h>
#include <math.h>
#include <stdint.h>

#define B_ 64
#define T_ 512
#define H_ 1024
#define E_ 512
#define V_ 32000
#define M_BT (B_ * T_)        // 32768

// ---------------- scratch (device globals; no allocation allowed) ----------------
__device__ float g_rnn_in[B_ * (E_ + H_)];
__device__ float g_bias_aT[H_ * B_];
__device__ float g_scores[M_BT];
__device__ float g_cat2[B_ * 2 * H_];
__device__ float g_part_bias[8 * B_ * H_];
__device__ float g_part_gi[8 * B_ * 3 * H_];
__device__ float g_part_gh[8 * B_ * 3 * H_];
__device__ __half g_enc_h[(size_t)M_BT * H_];    // 64 MB fp16
__device__ __half g_w_h[H_ * H_];                // 2 MB fp16

// ======================= helpers =======================
__device__ __forceinline__ uint32_t smem_u32(const void* p) {
    uint32_t a;
    asm("{ .reg .u64 t; cvta.to.shared.u64 t, %1; cvt.u32.u64 %0, t; }" : "=r"(a) : "l"(p));
    return a;
}
#define CP_ASYNC16(dst, src) \
    asm volatile("cp.async.cg.shared.global [%0], [%1], 16;" :: "r"(dst), "l"(src))
#define CP_COMMIT() asm volatile("cp.async.commit_group;" ::: "memory")
#define CP_WAIT2() asm volatile("cp.async.wait_group 2;" ::: "memory")
#define CP_WAIT1() asm volatile("cp.async.wait_group 1;" ::: "memory")
#define CP_WAIT0() asm volatile("cp.async.wait_group 0;" ::: "memory")

__device__ __forceinline__ void ldmx4(uint32_t* r, uint32_t addr) {
    asm volatile("ldmatrix.sync.aligned.m8n8.x4.shared.b16 {%0,%1,%2,%3}, [%4];"
                 : "=r"(r[0]), "=r"(r[1]), "=r"(r[2]), "=r"(r[3]) : "r"(addr));
}
// fp16 mma
__device__ __forceinline__ void mma16816h(float* d, const uint32_t* a, uint32_t b0, uint32_t b1) {
    asm volatile("mma.sync.aligned.m16n8k16.row.col.f32.f16.f16.f32 "
                 "{%0,%1,%2,%3}, {%4,%5,%6,%7}, {%8,%9}, {%0,%1,%2,%3};"
                 : "+f"(d[0]), "+f"(d[1]), "+f"(d[2]), "+f"(d[3])
                 : "r"(a[0]), "r"(a[1]), "r"(a[2]), "r"(a[3]), "r"(b0), "r"(b1));
}
// fp32 quad -> fp16 quad
__device__ __forceinline__ uint2 cvt_h16(float4 x) {
    __align__(8) __half h[4];
    h[0] = __float2half_rn(x.x); h[1] = __float2half_rn(x.y);
    h[2] = __float2half_rn(x.z); h[3] = __float2half_rn(x.w);
    return *reinterpret_cast<uint2*>(h);
}

// ======================= tiling constants =======================
#define KSTEP 32
#define ROWB 80
// energy v8: fp16 1-pass, chunk=256 (32x64 warp tiles), 4-stage ring, 1 barrier/iter
#define EN_K 64
#define EN_ROWB 144
#define EN_A_T (128 * EN_ROWB)         // 18432
#define EN_B_T (256 * EN_ROWB)         // 36864
#define EN_STAGE (EN_A_T + EN_B_T)     // 55296
#define EN_NSTAGE 4
#define EN_RED_OFF (EN_NSTAGE * EN_STAGE)    // 221184
#define SMEM_ENERGY (EN_RED_OFF + 512 * 4)   // 223232
// fc v2 (proven): fp16 1-pass, BN=128, inline fp32->fp16, 2 stages
#define FC_TA (64 * ROWB)              // 5120
#define FC_TB (128 * ROWB)             // 10240
#define FC_A 0
#define FC_B FC_TA
#define FC_STAGE (FC_TA + FC_TB)       // 15360
#define SMEM_FC (2 * FC_STAGE)         // 30720

#define ENC_BLOCKS ((M_BT * (H_ / 4)) / 256)   // 32768
#define W_BLOCKS ((H_ * (H_ / 4)) / 256)       // 1024

// ---------------- merged split: enc -> fp16, attn_W[:, H:] -> fp16 ----------------
__global__ void split_all_k(const float* __restrict__ enc,
                            const float* __restrict__ attnW,
                            __half* __restrict__ eh, __half* __restrict__ wh) {
    if (blockIdx.x < ENC_BLOCKS) {
        size_t i = (size_t)blockIdx.x * 256 + threadIdx.x;
        float4 x = reinterpret_cast<const float4*>(enc)[i];
        *reinterpret_cast<uint2*>(eh + 4 * i) = cvt_h16(x);
    } else {
        int i = (blockIdx.x - ENC_BLOCKS) * 256 + threadIdx.x;
        int r = i >> 8;
        int k4 = i & 255;
        float4 x = *(reinterpret_cast<const float4*>(attnW + (size_t)r * (2 * H_) + H_) + k4);
        *reinterpret_cast<uint2*>(wh + 4 * (size_t)i) = cvt_h16(x);
    }
}

// ---------------- embedding gather ----------------
__global__ void gather_emb_k(const int* __restrict__ x,
                             const float* __restrict__ embW,
                             float* __restrict__ rnn_in) {
    int b = blockIdx.x;
    int row = x[b];
    for (int e = threadIdx.x; e < E_; e += blockDim.x)
        rnn_in[b * (E_ + H_) + e] = embW[(size_t)row * E_ + e];
}

// ---------------- K-split M=64 GEMM (fp32, proven) ----------------
__global__ void gemm_m64_ks(const float* __restrict__ A, int lda,
                            const float* __restrict__ W, int ldw,
                            float* __restrict__ Cp, int ldc, int kc) {
    __shared__ float As[16][64];
    __shared__ float Ws[16][64];
    const int tid = threadIdx.x;
    const int n0 = blockIdx.x * 64;
    const int kk0 = blockIdx.y * kc;
    const int lrow = tid >> 2;
    const int kq = (tid & 3) * 4;
    const int ty = tid >> 4;
    const int tx = tid & 15;

    float acc[4][4] = {};
    for (int kk = kk0; kk < kk0 + kc; kk += 16) {
        float4 av = *(const float4*)&A[lrow * lda + kk + kq];
        float4 wv = *(const float4*)&W[(size_t)(n0 + lrow) * ldw + kk + kq];
        __syncthreads();
        As[kq + 0][lrow] = av.x; As[kq + 1][lrow] = av.y;
        As[kq + 2][lrow] = av.z; As[kq + 3][lrow] = av.w;
        Ws[kq + 0][lrow] = wv.x; Ws[kq + 1][lrow] = wv.y;
        Ws[kq + 2][lrow] = wv.z; Ws[kq + 3][lrow] = wv.w;
        __syncthreads();
        #pragma unroll
        for (int k = 0; k < 16; k++) {
            float4 a = *(const float4*)&As[k][ty * 4];
            float4 w = *(const float4*)&Ws[k][tx * 4];
            float af[4] = {a.x, a.y, a.z, a.w};
            float wf[4] = {w.x, w.y, w.z, w.w};
            #pragma unroll
            for (int i = 0; i < 4; i++)
                #pragma unroll
                for (int j = 0; j < 4; j++)
                    acc[i][j] = fmaf(af[i], wf[j], acc[i][j]);
        }
    }
    #pragma unroll
    for (int i = 0; i < 4; i++) {
        int m = blockIdx.y * 64 + ty * 4 + i;
        #pragma unroll
        for (int j = 0; j < 4; j++)
            Cp[(size_t)m * ldc + n0 + tx * 4 + j] = acc[i][j];
    }
}

// ---------------- bias partial reduce + transpose ----------------
__global__ void bias_redT_k(const float* __restrict__ part,
                            const float* __restrict__ attb,
                            float* __restrict__ biasT) {
    int idx = blockIdx.x * 256 + threadIdx.x;
    int b = idx >> 10, h = idx & 1023;
    float s = attb[h];
    #pragma unroll
    for (int ks = 0; ks < 8; ks++)
        s += part[(size_t)((ks << 6) + b) * H_ + h];
    biasT[h * B_ + b] = s;
}

// ---------------- energy GEMM v8: fp16 1-pass, chunk=256, 4-stage, 1 barrier/iter ----------------
__global__ void __launch_bounds__(512, 1)
energy_mma_k(const __half* __restrict__ eh, const __half* __restrict__ wh,
             const float* __restrict__ biasT, const float* __restrict__ v,
             float* __restrict__ scores) {
    extern __shared__ char sm[];
    const uint32_t sb = smem_u32(sm);
    float* red = (float*)(sm + EN_RED_OFF);

    const int tid = threadIdx.x;
    const int wid = tid >> 5;
    const int lane = tid & 31;
    const int m0 = blockIdx.x * 128;
    const int mw = wid >> 2;       // 0..3: rows mw*32..+31
    const int nw = wid & 3;        // 0..3: cols nw*64..+63 within 256-col chunk

    const int a_l = lane & 15;
    const int a_kh = (lane >> 4) << 3;
    const int b_nb = (lane & 7) + ((lane >> 4) << 3);
    const int b_kh = ((lane >> 3) & 1) << 3;
    const int g = lane >> 2;
    const int t2 = (lane & 3) << 1;

    float acc[2][8][4];
    float rowsum[4];
    #pragma unroll
    for (int i = 0; i < 4; i++) rowsum[i] = 0.f;

    const int total_it = 4 * 16;
    const int ar[2] = {tid >> 3, (tid + 512) >> 3};
    const int br[4] = {tid >> 3, (tid + 512) >> 3, (tid + 1024) >> 3, (tid + 1536) >> 3};
    const int cp_c = tid & 7;

    #define EN_CP(it_) do {                                                          \
        int chunk_ = (it_) >> 4;                                                     \
        int kb_ = ((it_) & 15) * EN_K;                                               \
        uint32_t stg_ = sb + ((it_) & 3) * EN_STAGE;                                 \
        _Pragma("unroll")                                                            \
        for (int j = 0; j < 2; j++)                                                  \
            CP_ASYNC16(stg_ + (uint32_t)(ar[j] * EN_ROWB + cp_c * 16),               \
                       eh + (size_t)(m0 + ar[j]) * H_ + kb_ + cp_c * 8);             \
        _Pragma("unroll")                                                            \
        for (int j = 0; j < 4; j++)                                                  \
            CP_ASYNC16(stg_ + EN_A_T + (uint32_t)(br[j] * EN_ROWB + cp_c * 16),      \
                       wh + (size_t)(chunk_ * 256 + br[j]) * H_ + kb_ + cp_c * 8);   \
        CP_COMMIT();                                                                 \
    } while (0)

    EN_CP(0);
    EN_CP(1);

    for (int it = 0; it < total_it; it++) {
        const int kt = it & 15;
        const int chunk = it >> 4;
        if (kt == 0) {
            #pragma unroll
            for (int mt = 0; mt < 2; mt++)
                #pragma unroll
                for (int nt = 0; nt < 8; nt++)
                    #pragma unroll
                    for (int k = 0; k < 4; k++) acc[mt][nt][k] = 0.f;
        }
        // single barrier per iter: write of stage (it+2)&3 is separated from its
        // last reads (iter it-2) by the barrier of iter it-1; barrier after wait
        // makes stage it&3 arrival visible block-wide.
        if (it + 2 < total_it) { EN_CP(it + 2); CP_WAIT2(); }
        else if (it + 1 < total_it) { CP_WAIT1(); }
        else { CP_WAIT0(); }
        __syncthreads();

        const uint32_t stg = sb + (it & 3) * EN_STAGE;
        #pragma unroll
        for (int ks = 0; ks < 4; ks++) {
            uint32_t Ah[2][4];
            #pragma unroll
            for (int mt = 0; mt < 2; mt++) {
                uint32_t off = (uint32_t)((mw * 32 + mt * 16 + a_l) * EN_ROWB + (ks * 16 + a_kh) * 2);
                ldmx4(Ah[mt], stg + off);
            }
            uint32_t Bh[4][4];
            #pragma unroll
            for (int np = 0; np < 4; np++) {
                uint32_t off = (uint32_t)((nw * 64 + np * 16 + b_nb) * EN_ROWB + (ks * 16 + b_kh) * 2);
                ldmx4(Bh[np], stg + EN_A_T + off);
            }
            #pragma unroll
            for (int mt = 0; mt < 2; mt++)
                #pragma unroll
                for (int np = 0; np < 4; np++) {
                    mma16816h(acc[mt][np * 2 + 0], Ah[mt], Bh[np][0], Bh[np][1]);
                    mma16816h(acc[mt][np * 2 + 1], Ah[mt], Bh[np][2], Bh[np][3]);
                }
        }

        if (kt == 15) {
            #pragma unroll
            for (int nt = 0; nt < 8; nt++) {
                const int col0 = chunk * 256 + nw * 64 + nt * 8 + t2;
                const float v0 = __ldg(&v[col0]);
                const float v1 = __ldg(&v[col0 + 1]);
                #pragma unroll
                for (int mt = 0; mt < 2; mt++) {
                    #pragma unroll
                    for (int i = 0; i < 2; i++) {
                        const int row = mw * 32 + mt * 16 + g + i * 8;
                        const int b = row & (B_ - 1);
                        float e0 = acc[mt][nt][i * 2 + 0] + __ldg(&biasT[(size_t)col0 * B_ + b]);
                        float e1 = acc[mt][nt][i * 2 + 1] + __ldg(&biasT[(size_t)(col0 + 1) * B_ + b]);
                        rowsum[mt * 2 + i] += fmaxf(e0, 0.f) * v0 + fmaxf(e1, 0.f) * v1;
                    }
                }
            }
        }
    }

    #pragma unroll
    for (int k = 0; k < 4; k++) {
        rowsum[k] += __shfl_xor_sync(0xFFFFFFFF, rowsum[k], 1);
        rowsum[k] += __shfl_xor_sync(0xFFFFFFFF, rowsum[k], 2);
    }
    __syncthreads();
    if ((lane & 3) == 0) {
        #pragma unroll
        for (int mt = 0; mt < 2; mt++)
            #pragma unroll
            for (int i = 0; i < 2; i++)
                red[nw * 128 + mw * 32 + mt * 16 + g + i * 8] = rowsum[mt * 2 + i];
    }
    __syncthreads();
    if (tid < 128) {
        float s = red[tid] + red[128 + tid] + red[256 + tid] + red[384 + tid];
        scores[m0 + tid] = s;
    }
    #undef EN_CP
}

// ---------------- fc GEMM v2 (proven): fp16 1-pass, BN=128, occ 2 ----------------
__global__ void __launch_bounds__(256, 2)
fc_mma_k(const float* __restrict__ cat2, const float* __restrict__ fcW,
         const float* __restrict__ fcb, float* __restrict__ logits) {
    extern __shared__ char sm[];
    const uint32_t sb = smem_u32(sm);

    const int tid = threadIdx.x;
    const int wid = tid >> 5;
    const int lane = tid & 31;
    const int n0 = blockIdx.x * 128;
    const int mw = wid >> 2;
    const int nw = wid & 3;

    const int a_l = lane & 15;
    const int a_kh = (lane >> 4) << 3;
    const int b_nb = (lane & 7) + ((lane >> 4) << 3);
    const int b_kh = ((lane >> 3) & 1) << 3;
    const int g = lane >> 2;
    const int t2 = (lane & 3) << 1;

    float acc[2][4][4];
    #pragma unroll
    for (int mt = 0; mt < 2; mt++)
        #pragma unroll
        for (int nt = 0; nt < 4; nt++)
            #pragma unroll
            for (int k = 0; k < 4; k++) acc[mt][nt][k] = 0.f;

    const int aro[2] = {tid >> 3, (tid + 256) >> 3};
    const int bro[4] = {tid >> 3, (tid + 256) >> 3, (tid + 512) >> 3, (tid + 768) >> 3};
    const int qc = tid & 7;
    float4 Ar[2], Br[4];

    #define FC_LDG(it_) do {                                                        \
        int kb_ = (it_) * KSTEP;                                                    \
        _Pragma("unroll")                                                           \
        for (int j = 0; j < 2; j++)                                                 \
            Ar[j] = *(const float4*)&cat2[(size_t)aro[j] * (2 * H_) + kb_ + qc * 4];\
        _Pragma("unroll")                                                           \
        for (int j = 0; j < 4; j++)                                                 \
            Br[j] = *(const float4*)&fcW[(size_t)(n0 + bro[j]) * (2 * H_) + kb_ + qc * 4]; \
    } while (0)

    #define FC_STS(it_) do {                                                        \
        char* st_ = sm + ((it_) & 1) * FC_STAGE;                                    \
        _Pragma("unroll")                                                           \
        for (int j = 0; j < 2; j++)                                                 \
            *reinterpret_cast<uint2*>(st_ + FC_A + aro[j] * ROWB + qc * 8) = cvt_h16(Ar[j]); \
        _Pragma("unroll")                                                           \
        for (int j = 0; j < 4; j++)                                                 \
            *reinterpret_cast<uint2*>(st_ + FC_B + bro[j] * ROWB + qc * 8) = cvt_h16(Br[j]); \
    } while (0)

    const int total_it = 64;
    FC_LDG(0);

    for (int it = 0; it < total_it; it++) {
        __syncthreads();
        FC_STS(it);
        if (it + 1 < total_it) FC_LDG(it + 1);
        __syncthreads();

        const uint32_t stg = sb + (it & 1) * FC_STAGE;
        #pragma unroll
        for (int ks = 0; ks < 2; ks++) {
            uint32_t Ah[2][4];
            #pragma unroll
            for (int mt = 0; mt < 2; mt++) {
                uint32_t off = (uint32_t)((mw * 32 + mt * 16 + a_l) * ROWB + (ks * 16 + a_kh) * 2);
                ldmx4(Ah[mt], stg + FC_A + off);
            }
            uint32_t Bh[2][4];
            #pragma unroll
            for (int np = 0; np < 2; np++) {
                uint32_t off = (uint32_t)((nw * 32 + np * 16 + b_nb) * ROWB + (ks * 16 + b_kh) * 2);
                ldmx4(Bh[np], stg + FC_B + off);
            }
            #pragma unroll
            for (int mt = 0; mt < 2; mt++)
                #pragma unroll
                for (int nt = 0; nt < 4; nt++) {
                    const int np = nt >> 1, pr = (nt & 1) * 2;
                    mma16816h(acc[mt][nt], Ah[mt], Bh[np][pr], Bh[np][pr + 1]);
                }
        }
    }

    #pragma unroll
    for (int nt = 0; nt < 4; nt++) {
        const int col0 = n0 + nw * 32 + nt * 8 + t2;
        const float c0 = __ldg(&fcb[col0]);
        const float c1 = __ldg(&fcb[col0 + 1]);
        #pragma unroll
        for (int mt = 0; mt < 2; mt++) {
            #pragma unroll
            for (int i = 0; i < 2; i++) {
                const int row = mw * 32 + mt * 16 + g + i * 8;
                float2 o;
                o.x = acc[mt][nt][i * 2 + 0] + c0;
                o.y = acc[mt][nt][i * 2 + 1] + c1;
                *reinterpret_cast<float2*>(&logits[(size_t)row * V_ + col0]) = o;
            }
        }
    }
    #undef FC_LDG
    #undef FC_STS
}

// ---------------- softmax over T ----------------
__global__ void softmax_k(const float* __restrict__ scores,
                          float* __restrict__ attn_w_out) {
    int b = blockIdx.x;
    int t = threadIdx.x;
    __shared__ float sh[512];
    float s = scores[t * B_ + b];
    sh[t] = s;
    __syncthreads();
    for (int off = 256; off > 0; off >>= 1) {
        if (t < off) sh[t] = fmaxf(sh[t], sh[t + off]);
        __syncthreads();
    }
    float mx = sh[0];
    __syncthreads();
    float e = expf(s - mx);
    sh[t] = e;
    __syncthreads();
    for (int off = 256; off > 0; off >>= 1) {
        if (t < off) sh[t] += sh[t + off];
        __syncthreads();
    }
    attn_w_out[b * T_ + t] = e / sh[0];
}

// ---------------- context = attn_w @ enc (float4, unroll 8) ----------------
__global__ void context_k(const float4* __restrict__ enc4,
                          const float* __restrict__ attn_w,
                          float* __restrict__ rnn_in,
                          float* __restrict__ cat2) {
    int b = blockIdx.y;
    int h4 = blockIdx.x * 128 + threadIdx.x;
    __shared__ float w[T_];
    for (int t = threadIdx.x; t < T_; t += 128) w[t] = attn_w[b * T_ + t];
    __syncthreads();
    float4 acc = {0.f, 0.f, 0.f, 0.f};
    #pragma unroll 8
    for (int t = 0; t < T_; t++) {
        float4 e = enc4[(size_t)(t * B_ + b) * (H_ / 4) + h4];
        float wt = w[t];
        acc.x = fmaf(wt, e.x, acc.x);
        acc.y = fmaf(wt, e.y, acc.y);
        acc.z = fmaf(wt, e.z, acc.z);
        acc.w = fmaf(wt, e.w, acc.w);
    }
    int h = h4 * 4;
    *reinterpret_cast<float4*>(&rnn_in[b * (E_ + H_) + E_ + h]) = acc;
    *reinterpret_cast<float4*>(&cat2[b * (2 * H_) + H_ + h]) = acc;
}

// ---------------- GRU gates (reduce 8 k-split partials) ----------------
__global__ void gates_k(const float* __restrict__ pgi,
                        const float* __restrict__ pgh,
                        const float* __restrict__ bih,
                        const float* __restrict__ bhh,
                        const float* __restrict__ lh,
                        float* __restrict__ hnew_out,
                        float* __restrict__ cat2) {
    int b = blockIdx.x;
    for (int h = threadIdx.x; h < H_; h += blockDim.x) {
        float gi0 = bih[h], gi1 = bih[H_ + h], gi2 = bih[2 * H_ + h];
        float gh0 = bhh[h], gh1 = bhh[H_ + h], gh2 = bhh[2 * H_ + h];
        #pragma unroll
        for (int ks = 0; ks < 8; ks++) {
            size_t base = (size_t)((ks << 6) + b) * 3 * H_;
            gi0 += pgi[base + h]; gi1 += pgi[base + H_ + h]; gi2 += pgi[base + 2 * H_ + h];
            gh0 += pgh[base + h]; gh1 += pgh[base + H_ + h]; gh2 += pgh[base + 2 * H_ + h];
        }
        float r = 1.f / (1.f + expf(-(gi0 + gh0)));
        float z = 1.f / (1.f + expf(-(gi1 + gh1)));
        float n = tanhf(gi2 + r * gh2);
        float hp = lh[b * H_ + h];
        float hn = (1.f - z) * n + z * hp;
        hnew_out[b * H_ + h] = hn;
        cat2[b * (2 * H_) + h] = hn;
    }
}

// ---------------- log_softmax in-place ----------------
__global__ void logsoftmax_k(float* __restrict__ logits) {
    int b = blockIdx.x;
    int tid = threadIdx.x;
    __shared__ float sh[1024];
    float* row = logits + (size_t)b * V_;
    float mx = -1e30f;
    for (int n = tid; n < V_; n += 1024) mx = fmaxf(mx, row[n]);
    sh[tid] = mx;
    __syncthreads();
    for (int off = 512; off > 0; off >>= 1) {
        if (tid < off) sh[tid] = fmaxf(sh[tid], sh[tid + off]);
        __syncthreads();
    }
    mx = sh[0];
    __syncthreads();
    float sum = 0.f;
    for (int n = tid; n < V_; n += 1024) sum += expf(row[n] - mx);
    sh[tid] = sum;
    __syncthreads();
    for (int off = 512; off > 0; off >>= 1) {
        if (tid < off) sh[tid] += sh[tid + off];
        __syncthreads();
    }
    float lse = mx + logf(sh[0]);
    for (int n = tid; n < V_; n += 1024) row[n] -= lse;
}

// ---------------- launch ----------------
extern "C" void kernel_launch(void* const* d_in, const int* in_sizes, int n_in,
                              void* d_out, int out_size) {
    const int*   x    = (const int*)d_in[0];
    const float* lh   = (const float*)d_in[1];
    const float* enc  = (const float*)d_in[2];
    const float* embW = (const float*)d_in[3];
    const float* attW = (const float*)d_in[4];
    const float* attb = (const float*)d_in[5];
    const float* v    = (const float*)d_in[6];
    const float* Wih  = (const float*)d_in[7];
    const float* Whh  = (const float*)d_in[8];
    const float* bih  = (const float*)d_in[9];
    const float* bhh  = (const float*)d_in[10];
    const float* fcW  = (const float*)d_in[11];
    const float* fcb  = (const float*)d_in[12];

    float* out      = (float*)d_out;
    float* out_logp = out;
    float* out_h    = out + (size_t)B_ * V_;
    float* out_w    = out_h + (size_t)B_ * H_;

    float *rnn_in, *bias_aT, *scoresp, *cat2, *pbias, *pgi, *pgh;
    __half *eh, *wh;
    cudaGetSymbolAddress((void**)&rnn_in,  g_rnn_in);
    cudaGetSymbolAddress((void**)&bias_aT, g_bias_aT);
    cudaGetSymbolAddress((void**)&scoresp, g_scores);
    cudaGetSymbolAddress((void**)&cat2,    g_cat2);
    cudaGetSymbolAddress((void**)&pbias,   g_part_bias);
    cudaGetSymbolAddress((void**)&pgi,     g_part_gi);
    cudaGetSymbolAddress((void**)&pgh,     g_part_gh);
    cudaGetSymbolAddress((void**)&eh,      g_enc_h);
    cudaGetSymbolAddress((void**)&wh,      g_w_h);

    cudaFuncSetAttribute(energy_mma_k, cudaFuncAttributeMaxDynamicSharedMemorySize, SMEM_ENERGY);
    cudaFuncSetAttribute(fc_mma_k, cudaFuncAttributeMaxDynamicSharedMemorySize, SMEM_FC);

    // launch order: energy_mma_k stays launch #4 (ncu captures the 4th launch)
    split_all_k<<<ENC_BLOCKS + W_BLOCKS, 256>>>(enc, attW, eh, wh);                   // 1
    gemm_m64_ks<<<dim3(H_ / 64, 8), 256>>>(lh, H_, attW, 2 * H_, pbias, H_, 128);     // 2
    bias_redT_k<<<(B_ * H_) / 256, 256>>>(pbias, attb, bias_aT);                      // 3
    energy_mma_k<<<M_BT / 128, 512, SMEM_ENERGY>>>(eh, wh, bias_aT, v, scoresp);      // 4
    gather_emb_k<<<B_, 128>>>(x, embW, rnn_in);                                       // 5
    softmax_k<<<B_, 512>>>(scoresp, out_w);
    context_k<<<dim3(2, B_), 128>>>((const float4*)enc, out_w, rnn_in, cat2);
    gemm_m64_ks<<<dim3(3 * H_ / 64, 8), 256>>>(rnn_in, E_ + H_, Wih, E_ + H_, pgi, 3 * H_, 192);
    gemm_m64_ks<<<dim3(3 * H_ / 64, 8), 256>>>(lh, H_, Whh, H_, pgh, 3 * H_, 128);
    gates_k<<<B_, 256>>>(pgi, pgh, bih, bhh, lh, out_h, cat2);
    fc_mma_k<<<V_ / 128, 256, SMEM_FC>>>(cat2, fcW, fcb, out_logp);
    logsoftmax_k<<<B_, 1024>>>(out_logp);
}